// round 1
// baseline (speedup 1.0000x reference)
#include <cuda_runtime.h>
#include <cstdint>

// Problem constants
#define T_C 4
#define N_C 20000
#define E_C 320000
#define FIN 12
#define EH 32
#define NH 64
#define GH 64

// ---------------- device scratch (module-load allocated, no runtime alloc) ----------------
__device__ float d_xenc[T_C * N_C * NH];     // encoded nodes [T,N,64]
__device__ float d_xsA [T_C * N_C * NH];     // layer0 xs, then xres (in-place +xenc)
__device__ float d_xsB [T_C * N_C * NH];     // layer1 xs
__device__ float d_es0 [(size_t)T_C * E_C * EH]; // layer0 e_new per step [T,E,32]
__device__ float d_e1  [(size_t)E_C * EH];   // layer1 edge carry (in-place)
__device__ float d_hx0 [N_C * NH];           // zeros (h_x at t=0)
__device__ float d_ns  [N_C * NH];           // per-node edge contributions (ns|nr)
__device__ float d_acc [N_C * NH];           // sent(0:32)|recv(32:64) scatter accumulator
__device__ float d_g[GH], d_gsave[GH];
__device__ float d_gce[EH];                  // global+bias const for edge block
__device__ float d_gcn[NH];                  // global+bias const for node block
__device__ float d_esum[EH], d_xsum[NH];
__device__ float d_Pp[EH], d_Pm[EH];
__device__ int   d_fast0;

// ---------------- kernels ----------------

// x_enc = relu(node_attr @ W_ne + b_ne), thread per (row, feature)
__global__ __launch_bounds__(256) void k_encode(const float* __restrict__ na,
                                                const float* __restrict__ W_ne,
                                                const float* __restrict__ b_ne,
                                                float* __restrict__ xenc) {
    __shared__ float sW[FIN * NH + NH];
    for (int i = threadIdx.x; i < FIN * NH + NH; i += 256)
        sW[i] = (i < FIN * NH) ? W_ne[i] : b_ne[i - FIN * NH];
    __syncthreads();
    int idx = blockIdx.x * 256 + threadIdx.x;     // 0 .. T*N*64
    int row = idx >> 6, j = idx & 63;
    float v = sW[FIN * NH + j];
#pragma unroll
    for (int k = 0; k < FIN; k++) v += na[row * FIN + k] * sW[k * NH + j];
    xenc[idx] = fmaxf(v, 0.f);
}

// Precompute P+/P- for layer-0 edge-encoder folding (valid iff b_ee == 0)
__global__ void k_prep(const float* __restrict__ W_ee, const float* __restrict__ b_ee,
                       const float* __restrict__ W_eb) {
    int j = threadIdx.x;  // 32
    float pp = 0.f, pm = 0.f;
    bool ok = true;
#pragma unroll
    for (int k = 0; k < EH; k++) {
        float w = W_ee[k];
        pp += fmaxf(w, 0.f)  * W_eb[k * EH + j];
        pm += fmaxf(-w, 0.f) * W_eb[k * EH + j];
        if (b_ee[k] != 0.f) ok = false;
    }
    d_Pp[j] = pp; d_Pm[j] = pm;
    if (j == 0) d_fast0 = ok ? 1 : 0;
}

// init global-derived constants from a given g0 (no relu on g0 itself)
__global__ void k_ginit(const float* __restrict__ g0,
                        const float* __restrict__ W_eb, const float* __restrict__ b_eb,
                        const float* __restrict__ W_nb, const float* __restrict__ b_nb) {
    __shared__ float g[GH];
    int tid = threadIdx.x;  // 96
    if (tid < GH) { g[tid] = g0[tid]; d_g[tid] = g0[tid]; }
    __syncthreads();
    if (tid < EH) {
        float v = b_eb[tid];
#pragma unroll
        for (int k = 0; k < GH; k++) v += g[k] * W_eb[(320 + k) * EH + tid];
        d_gce[tid] = v;
    } else if (tid < 32 + NH) {
        int j = tid - 32;
        float v = b_nb[j];
#pragma unroll
        for (int k = 0; k < GH; k++) v += g[k] * W_nb[(192 + k) * NH + j];
        d_gcn[j] = v;
    }
}

// Per-node sender/receiver contributions: ns|nr [N,64] from (x_in, h_x) @ W_eb rows 64..319
__global__ __launch_bounds__(256) void k_nodepre(const float* __restrict__ xin,
                                                 const float* __restrict__ hx,
                                                 const float* __restrict__ W_eb,
                                                 float* __restrict__ ns) {
    __shared__ float sW[256 * EH];  // 32 KB: rows 64..319 of W_eb
    for (int i = threadIdx.x; i < 256 * EH; i += 256) sW[i] = W_eb[64 * EH + i];
    __syncthreads();
    int lane = threadIdx.x & 31, wid = threadIdx.x >> 5;
    int n = blockIdx.x * 8 + wid;
    size_t b = (size_t)n * NH;
    float x0 = xin[b + lane], x1 = xin[b + 32 + lane];
    float h0 = hx[b + lane],  h1 = hx[b + 32 + lane];
    float aS = 0.f, aR = 0.f;
#pragma unroll
    for (int k = 0; k < 32; k++) {
        float v = __shfl_sync(0xffffffffu, x0, k);
        aS += v * sW[k * EH + lane];            // row 64+k
        aR += v * sW[(128 + k) * EH + lane];    // row 192+k
    }
#pragma unroll
    for (int k = 0; k < 32; k++) {
        float v = __shfl_sync(0xffffffffu, x1, k);
        aS += v * sW[(32 + k) * EH + lane];     // row 96+k
        aR += v * sW[(160 + k) * EH + lane];    // row 224+k
    }
#pragma unroll
    for (int k = 0; k < 32; k++) {
        float v = __shfl_sync(0xffffffffu, h0, k);
        aS += v * sW[(64 + k) * EH + lane];     // row 128+k
        aR += v * sW[(192 + k) * EH + lane];    // row 256+k
    }
#pragma unroll
    for (int k = 0; k < 32; k++) {
        float v = __shfl_sync(0xffffffffu, h1, k);
        aS += v * sW[(96 + k) * EH + lane];     // row 160+k
        aR += v * sW[(224 + k) * EH + lane];    // row 288+k
    }
    ns[b + lane] = aS;
    ns[b + 32 + lane] = aR;
}

// Edge block: e_new = relu(ein@We + he@Whe + ns[s] + nr[r] + gce); scatter into acc; esum
template <bool L0>
__global__ __launch_bounds__(256) void k_edge(const int* __restrict__ eidx,
                                              const float* __restrict__ ea_t,   // L0 only
                                              const float* __restrict__ ein,    // !L0 only
                                              const float* __restrict__ he,     // null if first
                                              float* __restrict__ eout,
                                              const float* __restrict__ ns,
                                              float* __restrict__ accbuf,
                                              const float* __restrict__ W_eb,
                                              const float* __restrict__ W_ee,
                                              const float* __restrict__ b_ee,
                                              int first) {
    __shared__ float sW[64 * EH];   // rows 0..63 of W_eb (e_in | h_e)
    __shared__ float sred[8 * EH];
    int tid = threadIdx.x;
    for (int i = tid; i < 64 * EH; i += 256) sW[i] = W_eb[i];
    int lane = tid & 31, wid = tid >> 5;
    float gce = d_gce[lane];
    float pp = 0.f, pm = 0.f, wee = 0.f, bee = 0.f;
    int fast = 0;
    if (L0) { fast = d_fast0; pp = d_Pp[lane]; pm = d_Pm[lane]; wee = W_ee[lane]; bee = b_ee[lane]; }
    __syncthreads();
    float esum = 0.f;
    int ebase = blockIdx.x * 32 + wid * 4;
#pragma unroll
    for (int i = 0; i < 4; i++) {
        int e = ebase + i;
        int s = eidx[e], r = eidx[E_C + e];
        float acc = gce;
        if (L0) {
            float a = ea_t[e];
            if (fast) {
                acc += (a >= 0.f) ? a * pp : -a * pm;
            } else {
                float v = fmaxf(a * wee + bee, 0.f);
#pragma unroll
                for (int k = 0; k < 32; k++)
                    acc += __shfl_sync(0xffffffffu, v, k) * sW[k * EH + lane];
            }
        } else {
            float v = ein[(size_t)e * EH + lane];
#pragma unroll
            for (int k = 0; k < 32; k++)
                acc += __shfl_sync(0xffffffffu, v, k) * sW[k * EH + lane];
        }
        if (!first) {
            float v = he[(size_t)e * EH + lane];
#pragma unroll
            for (int k = 0; k < 32; k++)
                acc += __shfl_sync(0xffffffffu, v, k) * sW[(32 + k) * EH + lane];
        }
        acc += ns[(size_t)s * NH + lane] + ns[(size_t)r * NH + 32 + lane];
        float en = fmaxf(acc, 0.f);
        eout[(size_t)e * EH + lane] = en;
        atomicAdd(&accbuf[(size_t)s * NH + lane], en);
        atomicAdd(&accbuf[(size_t)r * NH + 32 + lane], en);
        esum += en;
    }
    sred[wid * 32 + lane] = esum;
    __syncthreads();
    if (wid == 0) {
        float s2 = 0.f;
#pragma unroll
        for (int w = 0; w < 8; w++) s2 += sred[w * 32 + lane];
        atomicAdd(&d_esum[lane], s2);
    }
}

// Node block: x_new = relu(x@Wx + h@Wh + acc@Wsr + gcn); optional td; xsum accumulation
__global__ __launch_bounds__(256) void k_node(const float* __restrict__ xin,
                                              const float* __restrict__ hx,
                                              const float* __restrict__ accbuf,
                                              const float* __restrict__ W_nb,
                                              float* __restrict__ xsout,
                                              float* __restrict__ tdout /* nullable */) {
    extern __shared__ float sm[];
    float* sW = sm;                 // 192*64 floats
    float* sx = sm + 192 * NH;      // 8*64 staging
    int tid = threadIdx.x;
    for (int i = tid; i < 192 * NH; i += 256) sW[i] = W_nb[i];
    __syncthreads();
    int lane = tid & 31, wid = tid >> 5;
    int n = blockIdx.x * 8 + wid;
    size_t b = (size_t)n * NH;
    float x0 = xin[b + lane], x1 = xin[b + 32 + lane];
    float h0 = hx[b + lane],  h1 = hx[b + 32 + lane];
    float a0 = accbuf[b + lane], a1 = accbuf[b + 32 + lane];
    float lo = d_gcn[lane], hi = d_gcn[32 + lane];
#pragma unroll
    for (int k = 0; k < 32; k++) {
        float v = __shfl_sync(0xffffffffu, x0, k);
        lo += v * sW[k * NH + lane]; hi += v * sW[k * NH + 32 + lane];
    }
#pragma unroll
    for (int k = 0; k < 32; k++) {
        float v = __shfl_sync(0xffffffffu, x1, k);
        lo += v * sW[(32 + k) * NH + lane]; hi += v * sW[(32 + k) * NH + 32 + lane];
    }
#pragma unroll
    for (int k = 0; k < 32; k++) {
        float v = __shfl_sync(0xffffffffu, h0, k);
        lo += v * sW[(64 + k) * NH + lane]; hi += v * sW[(64 + k) * NH + 32 + lane];
    }
#pragma unroll
    for (int k = 0; k < 32; k++) {
        float v = __shfl_sync(0xffffffffu, h1, k);
        lo += v * sW[(96 + k) * NH + lane]; hi += v * sW[(96 + k) * NH + 32 + lane];
    }
#pragma unroll
    for (int k = 0; k < 32; k++) {
        float v = __shfl_sync(0xffffffffu, a0, k);
        lo += v * sW[(128 + k) * NH + lane]; hi += v * sW[(128 + k) * NH + 32 + lane];
    }
#pragma unroll
    for (int k = 0; k < 32; k++) {
        float v = __shfl_sync(0xffffffffu, a1, k);
        lo += v * sW[(160 + k) * NH + lane]; hi += v * sW[(160 + k) * NH + 32 + lane];
    }
    lo = fmaxf(lo, 0.f); hi = fmaxf(hi, 0.f);
    xsout[b + lane] = lo; xsout[b + 32 + lane] = hi;
    if (tdout) { tdout[b + lane] = lo - h0; tdout[b + 32 + lane] = hi - h1; }
    sx[wid * NH + lane] = lo; sx[wid * NH + 32 + lane] = hi;
    __syncthreads();
    if (tid < NH) {
        float s2 = 0.f;
#pragma unroll
        for (int w = 0; w < 8; w++) s2 += sx[w * NH + tid];
        atomicAdd(&d_xsum[tid], s2);
    }
}

// Global block: g_new = relu([xmean, emean, g] @ W_gb + b_gb); refresh gce/gcn; reset sums
__global__ void k_global(const float* __restrict__ W_gb, const float* __restrict__ b_gb,
                         const float* __restrict__ W_eb, const float* __restrict__ b_eb,
                         const float* __restrict__ W_nb, const float* __restrict__ b_nb,
                         int save) {
    __shared__ float gcat[160], gnew[GH];
    int tid = threadIdx.x;  // 256
    if (tid < 64) gcat[tid] = d_xsum[tid] * (1.0f / N_C);
    else if (tid < 96) gcat[tid] = d_esum[tid - 64] * (1.0f / E_C);
    else if (tid < 160) gcat[tid] = d_g[tid - 96];
    __syncthreads();
    if (tid < GH) {
        float v = b_gb[tid];
        for (int k = 0; k < 160; k++) v += gcat[k] * W_gb[k * GH + tid];
        gnew[tid] = fmaxf(v, 0.f);
    }
    __syncthreads();
    if (tid < GH) {
        d_g[tid] = gnew[tid];
        if (save) d_gsave[tid] = gnew[tid];
        d_xsum[tid] = 0.f;
    }
    if (tid < EH) d_esum[tid] = 0.f;
    if (tid < EH) {
        float v = b_eb[tid];
#pragma unroll
        for (int k = 0; k < GH; k++) v += gnew[k] * W_eb[(320 + k) * EH + tid];
        d_gce[tid] = v;
    } else if (tid < 32 + NH) {
        int j = tid - 32;
        float v = b_nb[j];
#pragma unroll
        for (int k = 0; k < GH; k++) v += gnew[k] * W_nb[(192 + k) * NH + j];
        d_gcn[j] = v;
    }
}

// s_der: sd[r] += coeff * spL[e] * (x[s] - x[r]) ; warp per edge (2 feats/lane)
__global__ __launch_bounds__(256) void k_sder(const int* __restrict__ eidx,
                                              const float* __restrict__ spL,
                                              const float* __restrict__ coeff,
                                              const float* __restrict__ xs,
                                              float* __restrict__ sd) {
    int tid = threadIdx.x, lane = tid & 31, wid = tid >> 5;
    int e = blockIdx.x * 8 + wid;
    int s = eidx[e], r = eidx[E_C + e];
    float cw = coeff[0] * spL[e];
    size_t bs = (size_t)s * NH, br = (size_t)r * NH;
    float d0 = cw * (xs[bs + lane] - xs[br + lane]);
    float d1 = cw * (xs[bs + 32 + lane] - xs[br + 32 + lane]);
    atomicAdd(&sd[br + lane], d0);
    atomicAdd(&sd[br + 32 + lane], d1);
}

// residual: xsA += xenc (elementwise, exact grid)
__global__ __launch_bounds__(256) void k_resid(float* __restrict__ a, const float* __restrict__ b) {
    int i = blockIdx.x * 256 + threadIdx.x;
    a[i] += b[i];
}

// decode: out = relu((xsA+xsB)@W1 + b1) @ W2 + b2 ; warp per row
__global__ __launch_bounds__(256) void k_decode(const float* __restrict__ xa,
                                                const float* __restrict__ xb,
                                                const float* __restrict__ W1,
                                                const float* __restrict__ b1,
                                                const float* __restrict__ W2,
                                                const float* __restrict__ b2,
                                                float* __restrict__ outn) {
    __shared__ float sW[NH * NH];
    __shared__ float sw2[NH];
    int tid = threadIdx.x;
    for (int i = tid; i < NH * NH; i += 256) sW[i] = W1[i];
    if (tid < NH) sw2[tid] = W2[tid];
    __syncthreads();
    int lane = tid & 31, wid = tid >> 5;
    int row = blockIdx.x * 8 + wid;
    size_t b = (size_t)row * NH;
    float x0 = xa[b + lane] + xb[b + lane];
    float x1 = xa[b + 32 + lane] + xb[b + 32 + lane];
    float lo = b1[lane], hi = b1[32 + lane];
#pragma unroll
    for (int k = 0; k < 32; k++) {
        float v = __shfl_sync(0xffffffffu, x0, k);
        lo += v * sW[k * NH + lane]; hi += v * sW[k * NH + 32 + lane];
    }
#pragma unroll
    for (int k = 0; k < 32; k++) {
        float v = __shfl_sync(0xffffffffu, x1, k);
        lo += v * sW[(32 + k) * NH + lane]; hi += v * sW[(32 + k) * NH + 32 + lane];
    }
    lo = fmaxf(lo, 0.f); hi = fmaxf(hi, 0.f);
    float p = lo * sw2[lane] + hi * sw2[32 + lane];
#pragma unroll
    for (int o = 16; o; o >>= 1) p += __shfl_down_sync(0xffffffffu, p, o);
    if (lane == 0) outn[row] = p + b2[0];
}

// ---------------- host launcher ----------------
extern "C" void kernel_launch(void* const* d_in, const int* in_sizes, int n_in,
                              void* d_out, int out_size) {
    const float* node_attr  = (const float*)d_in[0];
    const float* edge_attr  = (const float*)d_in[1];
    const int*   edge_index = (const int*)  d_in[2];
    const float* spL        = (const float*)d_in[3];
    const float* gattr      = (const float*)d_in[4];
    const float* coeff      = (const float*)d_in[5];
    const float* W_ee = (const float*)d_in[6];
    const float* b_ee = (const float*)d_in[7];
    const float* W_ne = (const float*)d_in[8];
    const float* b_ne = (const float*)d_in[9];
    const float* W_eb = (const float*)d_in[10];
    const float* b_eb = (const float*)d_in[11];
    const float* W_nb = (const float*)d_in[12];
    const float* b_nb = (const float*)d_in[13];
    const float* W_gb = (const float*)d_in[14];
    const float* b_gb = (const float*)d_in[15];
    const float* W_nd1 = (const float*)d_in[16];
    const float* b_nd1 = (const float*)d_in[17];
    const float* W_nd2 = (const float*)d_in[18];
    const float* b_nd2 = (const float*)d_in[19];

    float* out    = (float*)d_out;
    float* out_td = out + (size_t)T_C * N_C;
    float* out_sd = out_td + (size_t)T_C * N_C * NH;

    float *xenc, *xsA, *xsB, *es0, *e1, *hx0, *ns, *acc, *gsave, *esum, *xsum;
    cudaGetSymbolAddress((void**)&xenc, d_xenc);
    cudaGetSymbolAddress((void**)&xsA,  d_xsA);
    cudaGetSymbolAddress((void**)&xsB,  d_xsB);
    cudaGetSymbolAddress((void**)&es0,  d_es0);
    cudaGetSymbolAddress((void**)&e1,   d_e1);
    cudaGetSymbolAddress((void**)&hx0,  d_hx0);
    cudaGetSymbolAddress((void**)&ns,   d_ns);
    cudaGetSymbolAddress((void**)&acc,  d_acc);
    cudaGetSymbolAddress((void**)&gsave, d_gsave);
    cudaGetSymbolAddress((void**)&esum, d_esum);
    cudaGetSymbolAddress((void**)&xsum, d_xsum);

    const int NODE_SMEM = (192 * NH + 8 * NH) * (int)sizeof(float);  // 51200 B
    cudaFuncSetAttribute(k_node, cudaFuncAttributeMaxDynamicSharedMemorySize, NODE_SMEM);

    // launch-start zeroing (determinism; d_out is poisoned)
    cudaMemsetAsync(hx0, 0, (size_t)N_C * NH * sizeof(float));
    cudaMemsetAsync(esum, 0, EH * sizeof(float));
    cudaMemsetAsync(xsum, 0, NH * sizeof(float));
    cudaMemsetAsync(out_sd, 0, (size_t)T_C * N_C * NH * sizeof(float));

    k_encode<<<(T_C * N_C * NH) / 256, 256>>>(node_attr, W_ne, b_ne, xenc);
    k_prep<<<1, 32>>>(W_ee, b_ee, W_eb);

    // ---------------- layer 0 ----------------
    k_ginit<<<1, 96>>>(gattr, W_eb, b_eb, W_nb, b_nb);
    for (int t = 0; t < T_C; t++) {
        cudaMemsetAsync(acc, 0, (size_t)N_C * NH * sizeof(float));
        const float* xin = xenc + (size_t)t * N_C * NH;
        const float* hx = t ? (xsA + (size_t)(t - 1) * N_C * NH) : hx0;
        k_nodepre<<<N_C / 8, 256>>>(xin, hx, W_eb, ns);
        k_edge<true><<<E_C / 32, 256>>>(edge_index, edge_attr + (size_t)t * E_C, nullptr,
                                        t ? (es0 + (size_t)(t - 1) * E_C * EH) : nullptr,
                                        es0 + (size_t)t * E_C * EH, ns, acc,
                                        W_eb, W_ee, b_ee, t == 0);
        k_node<<<N_C / 8, 256, NODE_SMEM>>>(xin, hx, acc, W_nb,
                                            xsA + (size_t)t * N_C * NH, nullptr);
        if (t < T_C - 1 || t == 0) {
            // need g carry for t+1 and g_save at t==0 (t==0 covers both)
        }
        if (t < T_C - 1)
            k_global<<<1, 256>>>(W_gb, b_gb, W_eb, b_eb, W_nb, b_nb, t == 0 ? 1 : 0);
        else if (t == 0)
            k_global<<<1, 256>>>(W_gb, b_gb, W_eb, b_eb, W_nb, b_nb, 1);
    }

    // residual: xsA becomes x_res
    k_resid<<<(T_C * N_C * NH) / 256, 256>>>(xsA, xenc);

    // reset running sums (layer-0 t=3 accumulated without a global to clear them)
    cudaMemsetAsync(esum, 0, EH * sizeof(float));
    cudaMemsetAsync(xsum, 0, NH * sizeof(float));

    // ---------------- layer 1 ----------------
    k_ginit<<<1, 96>>>(gsave, W_eb, b_eb, W_nb, b_nb);
    for (int t = 0; t < T_C; t++) {
        cudaMemsetAsync(acc, 0, (size_t)N_C * NH * sizeof(float));
        const float* xin = xsA + (size_t)t * N_C * NH;
        const float* hx = t ? (xsB + (size_t)(t - 1) * N_C * NH) : hx0;
        k_nodepre<<<N_C / 8, 256>>>(xin, hx, W_eb, ns);
        k_edge<false><<<E_C / 32, 256>>>(edge_index, nullptr,
                                         es0 + (size_t)t * E_C * EH,
                                         t ? e1 : nullptr, e1, ns, acc,
                                         W_eb, W_ee, b_ee, t == 0);
        k_node<<<N_C / 8, 256, NODE_SMEM>>>(xin, hx, acc, W_nb,
                                            xsB + (size_t)t * N_C * NH,
                                            out_td + (size_t)t * N_C * NH);
        if (t < T_C - 1)
            k_global<<<1, 256>>>(W_gb, b_gb, W_eb, b_eb, W_nb, b_nb, 0);
        k_sder<<<E_C / 8, 256>>>(edge_index, spL, coeff,
                                 xsB + (size_t)t * N_C * NH,
                                 out_sd + (size_t)t * N_C * NH);
    }

    // decode
    k_decode<<<(T_C * N_C) / 8, 256>>>(xsA, xsB, W_nd1, b_nd1, W_nd2, b_nd2, out);
}